// round 1
// baseline (speedup 1.0000x reference)
#include <cuda_runtime.h>
#include <mma.h>

using namespace nvcuda;

// Problem constants
#define TOK   8192      // L*B
#define DDIM  1024
#define FDIM  4096
#define NEXP  8

// ---------------- device scratch (static, no allocation) ----------------
__device__ float g_h[(size_t)NEXP * 8192 * FDIM];   // GEMM1 output / silu(h)
__device__ float g_y[(size_t)NEXP * 8192 * DDIM];   // GEMM2 output (raw)
__device__ int   g_tok[NEXP * 8192];                // slot -> token id
__device__ float g_w[NEXP * 8192];                  // slot -> combine weight
__device__ int   g_slot[TOK * 2];                   // token -> 2 slots
__device__ float g_partial[1024 * NEXP];            // per-block softmax sums
__device__ float g_taskgate[NEXP];
__device__ int   g_cnt[NEXP];

// ---------------- tiny kernels ----------------
__global__ void k_init() {
    if (threadIdx.x < NEXP) g_cnt[threadIdx.x] = 0;
}

__global__ void k_taskgate(const float* __restrict__ task,
                           const float* __restrict__ Wgt,
                           const float* __restrict__ bgt) {
    __shared__ float red[256][8];
    float p[8];
#pragma unroll
    for (int e = 0; e < 8; e++) p[e] = 0.f;
    for (int d = threadIdx.x; d < DDIM; d += 256) {
        float tv = task[d];
#pragma unroll
        for (int e = 0; e < 8; e++) p[e] += tv * Wgt[d * 8 + e];
    }
#pragma unroll
    for (int e = 0; e < 8; e++) red[threadIdx.x][e] = p[e];
    __syncthreads();
    if (threadIdx.x < 8) {
        float s = bgt[threadIdx.x];
        for (int w = 0; w < 256; w++) s += red[w][threadIdx.x];
        g_taskgate[threadIdx.x] = s;
    }
}

// gating: one warp per token
__global__ void k_gate(const float* __restrict__ x,
                       const float* __restrict__ Wg,
                       const float* __restrict__ bg,
                       const float* __restrict__ alpha_p) {
    int warp = threadIdx.x >> 5, lane = threadIdx.x & 31;
    int t = blockIdx.x * 8 + warp;
    const float* xr = x + (size_t)t * DDIM;

    float acc[8];
#pragma unroll
    for (int e = 0; e < 8; e++) acc[e] = 0.f;
#pragma unroll 4
    for (int i = 0; i < 32; i++) {
        int d = i * 32 + lane;
        float xv = xr[d];
#pragma unroll
        for (int e = 0; e < 8; e++) acc[e] += xv * Wg[d * 8 + e];
    }
#pragma unroll
    for (int off = 16; off > 0; off >>= 1)
#pragma unroll
        for (int e = 0; e < 8; e++)
            acc[e] += __shfl_xor_sync(0xffffffffu, acc[e], off);

    float alpha = alpha_p[0];
    float logits[8];
#pragma unroll
    for (int e = 0; e < 8; e++) {
        float v = (1.f - alpha) * (acc[e] + bg[e]) + alpha * g_taskgate[e];
        if (!isfinite(v)) v = 0.f;
        logits[e] = v;
    }

    // full softmax (for aux loss) in fp32
    float m = logits[0];
#pragma unroll
    for (int e = 1; e < 8; e++) m = fmaxf(m, logits[e]);
    float ssum = 0.f, sm[8];
#pragma unroll
    for (int e = 0; e < 8; e++) { sm[e] = expf(logits[e] - m); ssum += sm[e]; }
    float inv = 1.f / ssum;
#pragma unroll
    for (int e = 0; e < 8; e++) sm[e] *= inv;

    // deterministic per-block softmax-sum reduction
    __shared__ float wsm[8][8];
#pragma unroll
    for (int e = 0; e < 8; e++) if (lane == e) wsm[warp][e] = sm[e];
    __syncthreads();
    if (threadIdx.x < 8) {
        float s2 = 0.f;
#pragma unroll
        for (int w = 0; w < 8; w++) s2 += wsm[w][threadIdx.x];
        g_partial[blockIdx.x * 8 + threadIdx.x] = s2;
    }

    // top-2 (ties -> lower index, matches jax.lax.top_k)
    float v0 = -1e30f; int i0 = 0;
#pragma unroll
    for (int e = 0; e < 8; e++) if (logits[e] > v0) { v0 = logits[e]; i0 = e; }
    float v1 = -1e30f; int i1 = 0;
#pragma unroll
    for (int e = 0; e < 8; e++) if (e != i0 && logits[e] > v1) { v1 = logits[e]; i1 = e; }

    float ew = expf(v1 - v0);
    float w0 = 1.f / (1.f + ew);
    float w1 = ew / (1.f + ew);

    if (lane == 0) {
        int p0 = atomicAdd(&g_cnt[i0], 1);
        int s0 = i0 * 8192 + p0;
        g_tok[s0] = t; g_w[s0] = w0; g_slot[t * 2 + 0] = s0;
        int p1 = atomicAdd(&g_cnt[i1], 1);
        int s1 = i1 * 8192 + p1;
        g_tok[s1] = t; g_w[s1] = w1; g_slot[t * 2 + 1] = s1;
    }
}

__global__ void k_laux(float* __restrict__ out, int out_size) {
    __shared__ float sw[8];
    if (threadIdx.x < 8) {
        float s = 0.f;
        for (int b = 0; b < 1024; b++) s += g_partial[b * 8 + threadIdx.x];
        sw[threadIdx.x] = s;
    }
    __syncthreads();
    if (threadIdx.x == 0) {
        float l = 0.f;
        for (int e = 0; e < 8; e++) l += sw[e] * (float)g_cnt[e];
        out[out_size - 1] = l / (8192.f * 8192.f);
    }
}

// ---------------- grouped GEMMs (tf32 WMMA, 128x128x16 tiles) ----------------
#define BM 128
#define BN 128
#define BK 16
#define LDA 20
#define LDB 132

// GEMM1: z[slot, F] = x[token(slot), :] @ W1[e]   (raw, no bias/act)
__global__ __launch_bounds__(256) void k_gemm1(const float* __restrict__ x,
                                               const float* __restrict__ W1) {
    int e = blockIdx.z;
    int cnt = g_cnt[e];
    int m0 = blockIdx.x * BM;
    if (m0 >= cnt) return;
    int n0 = blockIdx.y * BN;

    __shared__ float As[BM * LDA];
    __shared__ float Bs[BK * LDB];
    __shared__ int s_tok[BM];
    int tid = threadIdx.x;
    if (tid < BM) {
        int r = m0 + tid;
        s_tok[tid] = (r < cnt) ? g_tok[e * 8192 + r] : 0;
    }
    __syncthreads();

    int warp = tid >> 5;
    int warpM = warp >> 2;   // 0..1 (64-row group)
    int warpN = warp & 3;    // 0..3 (32-col group)

    wmma::fragment<wmma::accumulator, 16, 16, 8, float> acc[4][2];
#pragma unroll
    for (int mi = 0; mi < 4; mi++)
#pragma unroll
        for (int ni = 0; ni < 2; ni++) wmma::fill_fragment(acc[mi][ni], 0.f);

    const float* Wb = W1 + (size_t)e * DDIM * FDIM;

    for (int kt = 0; kt < DDIM; kt += BK) {
#pragma unroll
        for (int i = tid; i < BM * BK; i += 256) {
            int r = i >> 4, kk = i & 15;
            As[r * LDA + kk] = x[(size_t)s_tok[r] * DDIM + kt + kk];
        }
#pragma unroll
        for (int i = tid; i < BK * BN; i += 256) {
            int r = i >> 7, c = i & 127;
            Bs[r * LDB + c] = Wb[(size_t)(kt + r) * FDIM + n0 + c];
        }
        __syncthreads();
#pragma unroll
        for (int ks = 0; ks < BK; ks += 8) {
            wmma::fragment<wmma::matrix_a, 16, 16, 8, wmma::precision::tf32, wmma::row_major> a[4];
            wmma::fragment<wmma::matrix_b, 16, 16, 8, wmma::precision::tf32, wmma::row_major> b[2];
#pragma unroll
            for (int mi = 0; mi < 4; mi++) {
                wmma::load_matrix_sync(a[mi], &As[(warpM * 64 + mi * 16) * LDA + ks], LDA);
#pragma unroll
                for (int j = 0; j < a[mi].num_elements; j++)
                    a[mi].x[j] = wmma::__float_to_tf32(a[mi].x[j]);
            }
#pragma unroll
            for (int ni = 0; ni < 2; ni++) {
                wmma::load_matrix_sync(b[ni], &Bs[ks * LDB + warpN * 32 + ni * 16], LDB);
#pragma unroll
                for (int j = 0; j < b[ni].num_elements; j++)
                    b[ni].x[j] = wmma::__float_to_tf32(b[ni].x[j]);
            }
#pragma unroll
            for (int mi = 0; mi < 4; mi++)
#pragma unroll
                for (int ni = 0; ni < 2; ni++)
                    wmma::mma_sync(acc[mi][ni], a[mi], b[ni], acc[mi][ni]);
        }
        __syncthreads();
    }

    float* Hb = g_h + ((size_t)e * 8192 + m0) * FDIM;
#pragma unroll
    for (int mi = 0; mi < 4; mi++)
#pragma unroll
        for (int ni = 0; ni < 2; ni++) {
            int rr = warpM * 64 + mi * 16;
            int cc = n0 + warpN * 32 + ni * 16;
            wmma::store_matrix_sync(Hb + (size_t)rr * FDIM + cc, acc[mi][ni],
                                    FDIM, wmma::mem_row_major);
        }
}

// elementwise: h = silu(z + b1[e])
__global__ void k_silu(const float* __restrict__ b1) {
    int e = blockIdx.y;
    int cnt = g_cnt[e];
    int m0 = blockIdx.x * 128;
    if (m0 >= cnt) return;
    float4* H = (float4*)(g_h + ((size_t)e * 8192 + m0) * FDIM);
    const float4* B1 = (const float4*)(b1 + (size_t)e * FDIM);
    const int nv = 128 * (FDIM / 4);
    for (int i = threadIdx.x; i < nv; i += 256) {
        int cv = i & (FDIM / 4 - 1);
        float4 v = H[i];
        float4 bb = B1[cv];
        v.x += bb.x; v.y += bb.y; v.z += bb.z; v.w += bb.w;
        v.x = v.x / (1.f + __expf(-v.x));
        v.y = v.y / (1.f + __expf(-v.y));
        v.z = v.z / (1.f + __expf(-v.z));
        v.w = v.w / (1.f + __expf(-v.w));
        H[i] = v;
    }
}

// GEMM2: y[slot, D] = h[slot, :] @ W2[e]   (raw; b2 + weight applied in combine)
__global__ __launch_bounds__(256) void k_gemm2(const float* __restrict__ W2) {
    int e = blockIdx.z;
    int cnt = g_cnt[e];
    int m0 = blockIdx.x * BM;
    if (m0 >= cnt) return;
    int n0 = blockIdx.y * BN;

    __shared__ float As[BM * LDA];
    __shared__ float Bs[BK * LDB];
    int tid = threadIdx.x;

    int warp = tid >> 5;
    int warpM = warp >> 2;
    int warpN = warp & 3;

    wmma::fragment<wmma::accumulator, 16, 16, 8, float> acc[4][2];
#pragma unroll
    for (int mi = 0; mi < 4; mi++)
#pragma unroll
        for (int ni = 0; ni < 2; ni++) wmma::fill_fragment(acc[mi][ni], 0.f);

    const float* Hb = g_h + ((size_t)e * 8192 + m0) * FDIM;
    const float* Wb = W2 + (size_t)e * FDIM * DDIM;

    for (int kt = 0; kt < FDIM; kt += BK) {
#pragma unroll
        for (int i = tid; i < BM * BK; i += 256) {
            int r = i >> 4, kk = i & 15;
            As[r * LDA + kk] = Hb[(size_t)r * FDIM + kt + kk];
        }
#pragma unroll
        for (int i = tid; i < BK * BN; i += 256) {
            int r = i >> 7, c = i & 127;
            Bs[r * LDB + c] = Wb[(size_t)(kt + r) * DDIM + n0 + c];
        }
        __syncthreads();
#pragma unroll
        for (int ks = 0; ks < BK; ks += 8) {
            wmma::fragment<wmma::matrix_a, 16, 16, 8, wmma::precision::tf32, wmma::row_major> a[4];
            wmma::fragment<wmma::matrix_b, 16, 16, 8, wmma::precision::tf32, wmma::row_major> b[2];
#pragma unroll
            for (int mi = 0; mi < 4; mi++) {
                wmma::load_matrix_sync(a[mi], &As[(warpM * 64 + mi * 16) * LDA + ks], LDA);
#pragma unroll
                for (int j = 0; j < a[mi].num_elements; j++)
                    a[mi].x[j] = wmma::__float_to_tf32(a[mi].x[j]);
            }
#pragma unroll
            for (int ni = 0; ni < 2; ni++) {
                wmma::load_matrix_sync(b[ni], &Bs[ks * LDB + warpN * 32 + ni * 16], LDB);
#pragma unroll
                for (int j = 0; j < b[ni].num_elements; j++)
                    b[ni].x[j] = wmma::__float_to_tf32(b[ni].x[j]);
            }
#pragma unroll
            for (int mi = 0; mi < 4; mi++)
#pragma unroll
                for (int ni = 0; ni < 2; ni++)
                    wmma::mma_sync(acc[mi][ni], a[mi], b[ni], acc[mi][ni]);
        }
        __syncthreads();
    }

    float* Yb = g_y + ((size_t)e * 8192 + m0) * DDIM;
#pragma unroll
    for (int mi = 0; mi < 4; mi++)
#pragma unroll
        for (int ni = 0; ni < 2; ni++) {
            int rr = warpM * 64 + mi * 16;
            int cc = n0 + warpN * 32 + ni * 16;
            wmma::store_matrix_sync(Yb + (size_t)rr * DDIM + cc, acc[mi][ni],
                                    DDIM, wmma::mem_row_major);
        }
}

// out[t] = w0*(y[s0]+b2[e0]) + w1*(y[s1]+b2[e1])  — fixed order, no atomics
__global__ void k_combine(float* __restrict__ out, const float* __restrict__ b2) {
    int t = blockIdx.x;
    int s0 = g_slot[t * 2 + 0], s1 = g_slot[t * 2 + 1];
    float w0 = g_w[s0], w1 = g_w[s1];
    int e0 = s0 >> 13, e1 = s1 >> 13;
    const float4* y0 = (const float4*)(g_y + (size_t)s0 * DDIM);
    const float4* y1 = (const float4*)(g_y + (size_t)s1 * DDIM);
    const float4* b20 = (const float4*)(b2 + (size_t)e0 * DDIM);
    const float4* b21 = (const float4*)(b2 + (size_t)e1 * DDIM);
    float4* o = (float4*)(out + (size_t)t * DDIM);
    for (int i = threadIdx.x; i < DDIM / 4; i += 256) {
        float4 a = y0[i], b = y1[i], c0 = b20[i], c1 = b21[i];
        float4 r;
        r.x = w0 * (a.x + c0.x) + w1 * (b.x + c1.x);
        r.y = w0 * (a.y + c0.y) + w1 * (b.y + c1.y);
        r.z = w0 * (a.z + c0.z) + w1 * (b.z + c1.z);
        r.w = w0 * (a.w + c0.w) + w1 * (b.w + c1.w);
        o[i] = r;
    }
}

// ---------------- launch ----------------
extern "C" void kernel_launch(void* const* d_in, const int* in_sizes, int n_in,
                              void* d_out, int out_size) {
    const float* inputs  = (const float*)d_in[0];
    const float* task    = (const float*)d_in[1];
    const float* Wg_in   = (const float*)d_in[2];
    const float* bg_in   = (const float*)d_in[3];
    const float* Wg_task = (const float*)d_in[4];
    const float* bg_task = (const float*)d_in[5];
    const float* alpha   = (const float*)d_in[6];
    const float* W1      = (const float*)d_in[7];
    const float* b1      = (const float*)d_in[8];
    const float* W2      = (const float*)d_in[9];
    const float* b2      = (const float*)d_in[10];
    float* out = (float*)d_out;

    k_init<<<1, 32>>>();
    k_taskgate<<<1, 256>>>(task, Wg_task, bg_task);
    k_gate<<<1024, 256>>>(inputs, Wg_in, bg_in, alpha);
    k_laux<<<1, 32>>>(out, out_size);

    dim3 g1(64, 32, 8);
    k_gemm1<<<g1, 256>>>(inputs, W1);
    dim3 gs(64, 8);
    k_silu<<<gs, 256>>>(b1);
    dim3 g2(64, 8, 8);
    k_gemm2<<<g2, 256>>>(W2);
    k_combine<<<8192, 256>>>(out, b2);
}

// round 3
// speedup vs baseline: 3.0484x; 3.0484x over previous
#include <cuda_runtime.h>
#include <cstdint>

#define TOK   8192
#define DDIM  1024
#define FDIM  4096
#define NEXP  8

// ---------------- device scratch ----------------
__device__ float g_xr[(size_t)TOK * DDIM];            // tf32-rounded inputs
__device__ float g_h[(size_t)NEXP * 8192 * FDIM];     // silu(x@W1+b1), tf32-rounded
__device__ float g_y[(size_t)NEXP * 8192 * DDIM];     // raw expert output
__device__ float g_w1t[(size_t)NEXP * DDIM * FDIM];   // W1^T  [E][F][D], tf32-rounded
__device__ float g_w2t[(size_t)NEXP * DDIM * FDIM];   // W2^T  [E][D][F], tf32-rounded
__device__ int   g_tok[NEXP * 8192];
__device__ float g_w[NEXP * 8192];
__device__ int   g_slot[TOK * 2];
__device__ float g_partial[1024 * NEXP];
__device__ float g_taskgate[NEXP];
__device__ int   g_cnt[NEXP];

// ---------------- helpers ----------------
__device__ __forceinline__ uint32_t smem_to_u32(const void* p) {
    uint32_t a;
    asm("{ .reg .u64 t; cvta.to.shared.u64 t, %1; cvt.u32.u64 %0, t; }" : "=r"(a) : "l"(p));
    return a;
}
__device__ __forceinline__ float to_tf32(float x) {
    float r; asm("cvt.rna.tf32.f32 %0, %1;" : "=f"(r) : "f"(x)); return r;
}
__device__ __forceinline__ void cp16(uint32_t dst, const float* src) {
    asm volatile("cp.async.cg.shared.global [%0], [%1], 16;" :: "r"(dst), "l"(src));
}
#define CP_COMMIT() asm volatile("cp.async.commit_group;" ::: "memory")
#define CP_WAIT2()  asm volatile("cp.async.wait_group 2;" ::: "memory")

__device__ __forceinline__ uint32_t lds32(uint32_t a) {
    uint32_t v; asm("ld.shared.b32 %0, [%1];" : "=r"(v) : "r"(a)); return v;
}
__device__ __forceinline__ void mma8(float* d, const uint32_t* a, const uint32_t* b) {
    asm("mma.sync.aligned.m16n8k8.row.col.f32.tf32.tf32.f32 "
        "{%0,%1,%2,%3}, {%4,%5,%6,%7}, {%8,%9}, {%0,%1,%2,%3};"
        : "+f"(d[0]), "+f"(d[1]), "+f"(d[2]), "+f"(d[3])
        : "r"(a[0]), "r"(a[1]), "r"(a[2]), "r"(a[3]), "r"(b[0]), "r"(b[1]));
}

// ---------------- small kernels ----------------
__global__ void k_init() {
    if (threadIdx.x < NEXP) g_cnt[threadIdx.x] = 0;
}

__global__ void k_taskgate(const float* __restrict__ task,
                           const float* __restrict__ Wgt,
                           const float* __restrict__ bgt) {
    __shared__ float red[256][8];
    float p[8];
#pragma unroll
    for (int e = 0; e < 8; e++) p[e] = 0.f;
    for (int d = threadIdx.x; d < DDIM; d += 256) {
        float tv = task[d];
#pragma unroll
        for (int e = 0; e < 8; e++) p[e] += tv * Wgt[d * 8 + e];
    }
#pragma unroll
    for (int e = 0; e < 8; e++) red[threadIdx.x][e] = p[e];
    __syncthreads();
    if (threadIdx.x < 8) {
        float s = bgt[threadIdx.x];
        for (int w = 0; w < 256; w++) s += red[w][threadIdx.x];
        g_taskgate[threadIdx.x] = s;
    }
}

// gating: one warp per token; also writes tf32-rounded inputs to g_xr
__global__ void k_gate(const float* __restrict__ x,
                       const float* __restrict__ Wg,
                       const float* __restrict__ bg,
                       const float* __restrict__ alpha_p) {
    int warp = threadIdx.x >> 5, lane = threadIdx.x & 31;
    int t = blockIdx.x * 8 + warp;
    const float* xr = x + (size_t)t * DDIM;
    float* xw = g_xr + (size_t)t * DDIM;

    float acc[8];
#pragma unroll
    for (int e = 0; e < 8; e++) acc[e] = 0.f;
#pragma unroll 4
    for (int i = 0; i < 32; i++) {
        int d = i * 32 + lane;
        float xv = xr[d];
        xw[d] = to_tf32(xv);
#pragma unroll
        for (int e = 0; e < 8; e++) acc[e] += xv * Wg[d * 8 + e];
    }
#pragma unroll
    for (int off = 16; off > 0; off >>= 1)
#pragma unroll
        for (int e = 0; e < 8; e++)
            acc[e] += __shfl_xor_sync(0xffffffffu, acc[e], off);

    float alpha = alpha_p[0];
    float logits[8];
#pragma unroll
    for (int e = 0; e < 8; e++) {
        float v = (1.f - alpha) * (acc[e] + bg[e]) + alpha * g_taskgate[e];
        if (!isfinite(v)) v = 0.f;
        logits[e] = v;
    }

    float m = logits[0];
#pragma unroll
    for (int e = 1; e < 8; e++) m = fmaxf(m, logits[e]);
    float ssum = 0.f, sm[8];
#pragma unroll
    for (int e = 0; e < 8; e++) { sm[e] = expf(logits[e] - m); ssum += sm[e]; }
    float inv = 1.f / ssum;
#pragma unroll
    for (int e = 0; e < 8; e++) sm[e] *= inv;

    __shared__ float wsm[8][8];
#pragma unroll
    for (int e = 0; e < 8; e++) if (lane == e) wsm[warp][e] = sm[e];
    __syncthreads();
    if (threadIdx.x < 8) {
        float s2 = 0.f;
#pragma unroll
        for (int w = 0; w < 8; w++) s2 += wsm[w][threadIdx.x];
        g_partial[blockIdx.x * 8 + threadIdx.x] = s2;
    }

    float v0 = -1e30f; int i0 = 0;
#pragma unroll
    for (int e = 0; e < 8; e++) if (logits[e] > v0) { v0 = logits[e]; i0 = e; }
    float v1 = -1e30f; int i1 = 0;
#pragma unroll
    for (int e = 0; e < 8; e++) if (e != i0 && logits[e] > v1) { v1 = logits[e]; i1 = e; }

    float ew = expf(v1 - v0);
    float w0 = 1.f / (1.f + ew);
    float w1 = ew / (1.f + ew);

    if (lane == 0) {
        int p0 = atomicAdd(&g_cnt[i0], 1);
        int s0 = i0 * 8192 + p0;
        g_tok[s0] = t; g_w[s0] = w0; g_slot[t * 2 + 0] = s0;
        int p1 = atomicAdd(&g_cnt[i1], 1);
        int s1 = i1 * 8192 + p1;
        g_tok[s1] = t; g_w[s1] = w1; g_slot[t * 2 + 1] = s1;
    }
}

__global__ void k_laux(float* __restrict__ out, int out_size) {
    __shared__ float red[256];
    __shared__ float sw[8];
    int tid = threadIdx.x;
    int e = tid & 7, p = tid >> 3;
    float s = 0.f;
    for (int b = p; b < 1024; b += 32) s += g_partial[b * 8 + e];
    red[tid] = s;
    __syncthreads();
    if (tid < 8) {
        float t = 0.f;
        for (int q = 0; q < 32; q++) t += red[(q << 3) | tid];
        sw[tid] = t * (float)g_cnt[tid];
    }
    __syncthreads();
    if (tid == 0) {
        float l = 0.f;
        for (int i = 0; i < 8; i++) l += sw[i];
        out[out_size - 1] = l / (8192.f * 8192.f);
    }
}

// ---------------- weight transpose (with tf32 rounding) ----------------
template<bool FIRST>
__global__ void k_tr(const float* __restrict__ src) {
    constexpr int R = FIRST ? DDIM : FDIM;   // src rows (K dim)
    constexpr int C = FIRST ? FDIM : DDIM;   // src cols (N dim)
    float* dst = FIRST ? g_w1t : g_w2t;      // [C][R] per expert
    __shared__ float t[32][33];
    int e = blockIdx.z;
    int c0 = blockIdx.x * 32, r0 = blockIdx.y * 32;
    const float* s = src + (size_t)e * R * C;
    float* d = dst + (size_t)e * R * C;
    int tx = threadIdx.x & 31, ty = threadIdx.x >> 5;
#pragma unroll
    for (int i = 0; i < 32; i += 8)
        t[ty + i][tx] = to_tf32(s[(size_t)(r0 + ty + i) * C + c0 + tx]);
    __syncthreads();
#pragma unroll
    for (int i = 0; i < 32; i += 8)
        d[(size_t)(c0 + ty + i) * R + r0 + tx] = t[tx][ty + i];
}

// ---------------- tf32 mma.sync grouped GEMM ----------------
// Tile 128(M) x 256(N) x 32(K). 512 threads, warp grid 2x8, warp tile 64x32.
// 4-stage cp.async pipeline, 48KB/stage (A 16KB + B 32KB), XOR-swizzled smem.
#define STAGE_BYTES 49152
#define SMEM_DYN (4 * STAGE_BYTES)

template<bool G1>
__global__ __launch_bounds__(512, 1) void k_gemm(const float* __restrict__ bias) {
    constexpr int KD = G1 ? DDIM : FDIM;
    constexpr int ND = G1 ? FDIM : DDIM;
    constexpr int NC = KD / 32;

    int e = blockIdx.z;
    int cnt = g_cnt[e];
    int m0 = blockIdx.x * 128;
    if (m0 >= cnt) return;
    int n0 = blockIdx.y * 256;

    const float* Be = (G1 ? g_w1t : g_w2t) + (size_t)e * ((size_t)KD * ND);
    float* Out = G1 ? g_h : g_y;

    extern __shared__ float smem[];
    uint32_t sbase = smem_to_u32(smem);

    int tid = threadIdx.x;
    int lane = tid & 31, warp = tid >> 5;
    int wm = warp >> 3, wn = warp & 7;
    int gid = lane >> 2, tig = lane & 3;

    // ---- cp.async address precompute ----
    int ra = tid >> 3, ss = tid & 7;
    const float *srcA0, *srcA1;
    if (G1) {
        int r0 = m0 + ra, r1 = r0 + 64;
        int t0 = (r0 < cnt) ? g_tok[e * 8192 + r0] : 0;
        int t1 = (r1 < cnt) ? g_tok[e * 8192 + r1] : 0;
        srcA0 = g_xr + (size_t)t0 * KD + ss * 4;
        srcA1 = g_xr + (size_t)t1 * KD + ss * 4;
    } else {
        srcA0 = g_h + (size_t)(e * 8192 + m0 + ra) * KD + ss * 4;
        srcA1 = srcA0 + (size_t)64 * KD;
    }
    uint32_t dA0 = (uint32_t)(ra * 128 + ((ss ^ (ra & 7)) << 4));
    uint32_t dA1 = dA0 + 64 * 128;
    const float* srcB[4];
    uint32_t dB[4];
#pragma unroll
    for (int j = 0; j < 4; j++) {
        int n = ra + j * 64;
        srcB[j] = Be + (size_t)(n0 + n) * KD + ss * 4;
        dB[j] = (uint32_t)(16384 + n * 128 + ((ss ^ (n & 7)) << 4));
    }

    // ---- fragment LDS offsets (within a stage) ----
    uint32_t rowA[4], rowB[4];
#pragma unroll
    for (int mi = 0; mi < 4; mi++)
        rowA[mi] = (uint32_t)((wm * 64 + mi * 16 + gid) * 128 + tig * 4);
#pragma unroll
    for (int ni = 0; ni < 4; ni++)
        rowB[ni] = (uint32_t)(16384 + (wn * 32 + ni * 8 + gid) * 128 + tig * 4);

    float acc[4][4][4];
#pragma unroll
    for (int mi = 0; mi < 4; mi++)
#pragma unroll
        for (int ni = 0; ni < 4; ni++)
#pragma unroll
            for (int q = 0; q < 4; q++) acc[mi][ni][q] = 0.f;

    auto issue = [&](int slot, int kt) {
        uint32_t st = sbase + (uint32_t)slot * STAGE_BYTES;
        cp16(st + dA0, srcA0 + kt);
        cp16(st + dA1, srcA1 + kt);
#pragma unroll
        for (int j = 0; j < 4; j++) cp16(st + dB[j], srcB[j] + kt);
    };

    issue(0, 0);  CP_COMMIT();
    issue(1, 32); CP_COMMIT();
    issue(2, 64); CP_COMMIT();

#pragma unroll 1
    for (int c = 0; c < NC; c++) {
        CP_WAIT2();
        __syncthreads();
        int pf = c + 3;
        if (pf < NC) issue(pf & 3, pf * 32);
        CP_COMMIT();

        uint32_t st = sbase + (uint32_t)(c & 3) * STAGE_BYTES;
#pragma unroll
        for (int ks = 0; ks < 4; ks++) {
            uint32_t x0 = (uint32_t)((2 * ks) ^ gid) << 4;
            uint32_t x1 = x0 ^ 16u;
            uint32_t a[4][4], b[4][2];
#pragma unroll
            for (int mi = 0; mi < 4; mi++) {
                uint32_t base = st + rowA[mi];
                a[mi][0] = lds32(base + x0);
                a[mi][1] = lds32(base + 1024 + x0);
                a[mi][2] = lds32(base + x1);
                a[mi][3] = lds32(base + 1024 + x1);
            }
#pragma unroll
            for (int ni = 0; ni < 4; ni++) {
                uint32_t base = st + rowB[ni];
                b[ni][0] = lds32(base + x0);
                b[ni][1] = lds32(base + x1);
            }
#pragma unroll
            for (int mi = 0; mi < 4; mi++)
#pragma unroll
                for (int ni = 0; ni < 4; ni++)
                    mma8(acc[mi][ni], a[mi], b[ni]);
        }
    }

    // ---- epilogue ----
    const float* bptr = G1 ? (bias + (size_t)e * ND) : (const float*)nullptr;
#pragma unroll
    for (int mi = 0; mi < 4; mi++) {
        int gr0 = m0 + wm * 64 + mi * 16 + gid;
        int gr1 = gr0 + 8;
        bool v0 = gr0 < cnt, v1 = gr1 < cnt;
        float* o0 = Out + (size_t)(e * 8192 + gr0) * ND;
        float* o1 = Out + (size_t)(e * 8192 + gr1) * ND;
#pragma unroll
        for (int ni = 0; ni < 4; ni++) {
            int gc = n0 + wn * 32 + ni * 8 + tig * 2;
            float2 p0 = make_float2(acc[mi][ni][0], acc[mi][ni][1]);
            float2 p1 = make_float2(acc[mi][ni][2], acc[mi][ni][3]);
            if (G1) {
                float bb0 = bptr[gc], bb1 = bptr[gc + 1];
                p0.x += bb0; p0.y += bb1;
                p1.x += bb0; p1.y += bb1;
                p0.x = to_tf32(p0.x / (1.f + __expf(-p0.x)));
                p0.y = to_tf32(p0.y / (1.f + __expf(-p0.y)));
                p1.x = to_tf32(p1.x / (1.f + __expf(-p1.x)));
                p1.y = to_tf32(p1.y / (1.f + __expf(-p1.y)));
            }
            if (v0) *(float2*)(o0 + gc) = p0;
            if (v1) *(float2*)(o1 + gc) = p1;
        }
    }
}

// ---------------- combine ----------------
__global__ void k_combine(float* __restrict__ out, const float* __restrict__ b2) {
    int t = blockIdx.x;
    int s0 = g_slot[t * 2 + 0], s1 = g_slot[t * 2 + 1];
    float w0 = g_w[s0], w1 = g_w[s1];
    int e0 = s0 >> 13, e1 = s1 >> 13;
    const float4* y0 = (const float4*)(g_y + (size_t)s0 * DDIM);
    const float4* y1 = (const float4*)(g_y + (size_t)s1 * DDIM);
    const float4* b20 = (const float4*)(b2 + (size_t)e0 * DDIM);
    const float4* b21 = (const float4*)(b2 + (size_t)e1 * DDIM);
    float4* o = (float4*)(out + (size_t)t * DDIM);
    for (int i = threadIdx.x; i < DDIM / 4; i += 256) {
        float4 a = y0[i], b = y1[i], c0 = b20[i], c1 = b21[i];
        float4 r;
        r.x = w0 * (a.x + c0.x) + w1 * (b.x + c1.x);
        r.y = w0 * (a.y + c0.y) + w1 * (b.y + c1.y);
        r.z = w0 * (a.z + c0.z) + w1 * (b.z + c1.z);
        r.w = w0 * (a.w + c0.w) + w1 * (b.w + c1.w);
        o[i] = r;
    }
}

// ---------------- launch ----------------
extern "C" void kernel_launch(void* const* d_in, const int* in_sizes, int n_in,
                              void* d_out, int out_size) {
    const float* inputs  = (const float*)d_in[0];
    const float* task    = (const float*)d_in[1];
    const float* Wg_in   = (const float*)d_in[2];
    const float* bg_in   = (const float*)d_in[3];
    const float* Wg_task = (const float*)d_in[4];
    const float* bg_task = (const float*)d_in[5];
    const float* alpha   = (const float*)d_in[6];
    const float* W1      = (const float*)d_in[7];
    const float* b1      = (const float*)d_in[8];
    const float* W2      = (const float*)d_in[9];
    const float* b2      = (const float*)d_in[10];
    float* out = (float*)d_out;

    static bool attr_done = false;
    cudaFuncSetAttribute(k_gemm<true>,  cudaFuncAttributeMaxDynamicSharedMemorySize, SMEM_DYN);
    cudaFuncSetAttribute(k_gemm<false>, cudaFuncAttributeMaxDynamicSharedMemorySize, SMEM_DYN);
    (void)attr_done;

    k_init<<<1, 32>>>();
    k_taskgate<<<1, 256>>>(task, Wg_task, bg_task);
    k_gate<<<1024, 256>>>(inputs, Wg_in, bg_in, alpha);
    k_laux<<<1, 256>>>(out, out_size);

    // weight transposes (tf32-rounded)
    k_tr<true><<<dim3(FDIM / 32, DDIM / 32, NEXP), 256>>>(W1);
    k_tr<false><<<dim3(DDIM / 32, FDIM / 32, NEXP), 256>>>(W2);

    // grouped GEMMs
    k_gemm<true><<<dim3(64, FDIM / 256, NEXP), 512, SMEM_DYN>>>(b1);
    k_gemm<false><<<dim3(64, DDIM / 256, NEXP), 512, SMEM_DYN>>>(nullptr);

    k_combine<<<TOK, 256>>>(out, b2);
}

// round 4
// speedup vs baseline: 4.8062x; 1.5767x over previous
#include <cuda_runtime.h>
#include <cuda_fp16.h>
#include <cstdint>

#define TOK   8192
#define DDIM  1024
#define FDIM  4096
#define NEXP  8

// ---------------- device scratch ----------------
__device__ __half g_xh[(size_t)TOK * DDIM];             // fp16 inputs
__device__ __half g_h[(size_t)NEXP * 8192 * FDIM];      // fp16 silu(x@W1+b1)
__device__ float  g_y[(size_t)NEXP * 8192 * DDIM];      // raw expert output (fp32)
__device__ __half g_w1t[(size_t)NEXP * DDIM * FDIM];    // W1^T [E][F][D] fp16
__device__ __half g_w2t[(size_t)NEXP * DDIM * FDIM];    // W2^T [E][D][F] fp16
__device__ int    g_tok[NEXP * 8192];
__device__ float  g_w[NEXP * 8192];
__device__ int    g_slot[TOK * 2];
__device__ float  g_partial[1024 * NEXP];
__device__ float  g_taskgate[NEXP];
__device__ int    g_cnt[NEXP];

// ---------------- helpers ----------------
__device__ __forceinline__ uint32_t smem_to_u32(const void* p) {
    uint32_t a;
    asm("{ .reg .u64 t; cvta.to.shared.u64 t, %1; cvt.u32.u64 %0, t; }" : "=r"(a) : "l"(p));
    return a;
}
__device__ __forceinline__ void cp16(uint32_t dst, const void* src) {
    asm volatile("cp.async.cg.shared.global [%0], [%1], 16;" :: "r"(dst), "l"(src));
}
#define CP_COMMIT() asm volatile("cp.async.commit_group;" ::: "memory")
#define CP_WAIT2()  asm volatile("cp.async.wait_group 2;" ::: "memory")

__device__ __forceinline__ uint32_t lds32(uint32_t a) {
    uint32_t v; asm("ld.shared.b32 %0, [%1];" : "=r"(v) : "r"(a)); return v;
}
// fp16 MMA, fp32 accumulate: D(16x8) += A(16x16) * B(16x8)
__device__ __forceinline__ void mma16(float* d, const uint32_t* a, const uint32_t* b) {
    asm("mma.sync.aligned.m16n8k16.row.col.f32.f16.f16.f32 "
        "{%0,%1,%2,%3}, {%4,%5,%6,%7}, {%8,%9}, {%0,%1,%2,%3};"
        : "+f"(d[0]), "+f"(d[1]), "+f"(d[2]), "+f"(d[3])
        : "r"(a[0]), "r"(a[1]), "r"(a[2]), "r"(a[3]), "r"(b[0]), "r"(b[1]));
}

// ---------------- small kernels ----------------
__global__ void k_init() {
    if (threadIdx.x < NEXP) g_cnt[threadIdx.x] = 0;
}

__global__ void k_taskgate(const float* __restrict__ task,
                           const float* __restrict__ Wgt,
                           const float* __restrict__ bgt) {
    __shared__ float red[256][8];
    float p[8];
#pragma unroll
    for (int e = 0; e < 8; e++) p[e] = 0.f;
    for (int d = threadIdx.x; d < DDIM; d += 256) {
        float tv = task[d];
#pragma unroll
        for (int e = 0; e < 8; e++) p[e] += tv * Wgt[d * 8 + e];
    }
#pragma unroll
    for (int e = 0; e < 8; e++) red[threadIdx.x][e] = p[e];
    __syncthreads();
    if (threadIdx.x < 8) {
        float s = bgt[threadIdx.x];
        for (int w = 0; w < 256; w++) s += red[w][threadIdx.x];
        g_taskgate[threadIdx.x] = s;
    }
}

// gating: one warp per token; also writes fp16 inputs to g_xh
__global__ void k_gate(const float* __restrict__ x,
                       const float* __restrict__ Wg,
                       const float* __restrict__ bg,
                       const float* __restrict__ alpha_p) {
    int warp = threadIdx.x >> 5, lane = threadIdx.x & 31;
    int t = blockIdx.x * 8 + warp;
    const float* xr = x + (size_t)t * DDIM;
    __half* xw = g_xh + (size_t)t * DDIM;

    float acc[8];
#pragma unroll
    for (int e = 0; e < 8; e++) acc[e] = 0.f;
#pragma unroll 4
    for (int i = 0; i < 32; i++) {
        int d = i * 32 + lane;
        float xv = xr[d];
        xw[d] = __float2half_rn(xv);
#pragma unroll
        for (int e = 0; e < 8; e++) acc[e] += xv * Wg[d * 8 + e];
    }
#pragma unroll
    for (int off = 16; off > 0; off >>= 1)
#pragma unroll
        for (int e = 0; e < 8; e++)
            acc[e] += __shfl_xor_sync(0xffffffffu, acc[e], off);

    float alpha = alpha_p[0];
    float logits[8];
#pragma unroll
    for (int e = 0; e < 8; e++) {
        float v = (1.f - alpha) * (acc[e] + bg[e]) + alpha * g_taskgate[e];
        if (!isfinite(v)) v = 0.f;
        logits[e] = v;
    }

    float m = logits[0];
#pragma unroll
    for (int e = 1; e < 8; e++) m = fmaxf(m, logits[e]);
    float ssum = 0.f, sm[8];
#pragma unroll
    for (int e = 0; e < 8; e++) { sm[e] = expf(logits[e] - m); ssum += sm[e]; }
    float inv = 1.f / ssum;
#pragma unroll
    for (int e = 0; e < 8; e++) sm[e] *= inv;

    __shared__ float wsm[8][8];
#pragma unroll
    for (int e = 0; e < 8; e++) if (lane == e) wsm[warp][e] = sm[e];
    __syncthreads();
    if (threadIdx.x < 8) {
        float s2 = 0.f;
#pragma unroll
        for (int w = 0; w < 8; w++) s2 += wsm[w][threadIdx.x];
        g_partial[blockIdx.x * 8 + threadIdx.x] = s2;
    }

    float v0 = -1e30f; int i0 = 0;
#pragma unroll
    for (int e = 0; e < 8; e++) if (logits[e] > v0) { v0 = logits[e]; i0 = e; }
    float v1 = -1e30f; int i1 = 0;
#pragma unroll
    for (int e = 0; e < 8; e++) if (e != i0 && logits[e] > v1) { v1 = logits[e]; i1 = e; }

    float ew = expf(v1 - v0);
    float w0 = 1.f / (1.f + ew);
    float w1 = ew / (1.f + ew);

    if (lane == 0) {
        int p0 = atomicAdd(&g_cnt[i0], 1);
        int s0 = i0 * 8192 + p0;
        g_tok[s0] = t; g_w[s0] = w0; g_slot[t * 2 + 0] = s0;
        int p1 = atomicAdd(&g_cnt[i1], 1);
        int s1 = i1 * 8192 + p1;
        g_tok[s1] = t; g_w[s1] = w1; g_slot[t * 2 + 1] = s1;
    }
}

__global__ void k_laux(float* __restrict__ out, int out_size) {
    __shared__ float red[256];
    __shared__ float sw[8];
    int tid = threadIdx.x;
    int e = tid & 7, p = tid >> 3;
    float s = 0.f;
    for (int b = p; b < 1024; b += 32) s += g_partial[b * 8 + e];
    red[tid] = s;
    __syncthreads();
    if (tid < 8) {
        float t = 0.f;
        for (int q = 0; q < 32; q++) t += red[(q << 3) | tid];
        sw[tid] = t * (float)g_cnt[tid];
    }
    __syncthreads();
    if (tid == 0) {
        float l = 0.f;
        for (int i = 0; i < 8; i++) l += sw[i];
        out[out_size - 1] = l / (8192.f * 8192.f);
    }
}

// ---------------- weight transpose (fp32 -> fp16) ----------------
template<bool FIRST>
__global__ void k_tr(const float* __restrict__ src) {
    constexpr int R = FIRST ? DDIM : FDIM;   // src rows (K dim)
    constexpr int C = FIRST ? FDIM : DDIM;   // src cols (N dim)
    __half* dst = FIRST ? g_w1t : g_w2t;     // [C][R] per expert
    __shared__ float t[32][33];
    int e = blockIdx.z;
    int c0 = blockIdx.x * 32, r0 = blockIdx.y * 32;
    const float* s = src + (size_t)e * R * C;
    __half* d = dst + (size_t)e * R * C;
    int tx = threadIdx.x & 31, ty = threadIdx.x >> 5;
#pragma unroll
    for (int i = 0; i < 32; i += 8)
        t[ty + i][tx] = s[(size_t)(r0 + ty + i) * C + c0 + tx];
    __syncthreads();
#pragma unroll
    for (int i = 0; i < 32; i += 8)
        d[(size_t)(c0 + ty + i) * R + r0 + tx] = __float2half_rn(t[tx][ty + i]);
}

// ---------------- fp16 mma.sync grouped GEMM ----------------
// Tile 128(M) x 256(N) x 32(K). 512 threads, warp grid 2x8, warp tile 64x32.
// 4-stage cp.async pipeline. Stage = A 8KB + B 16KB = 24KB.
// Smem row = 64B (32 halves), XOR swizzle: seg' = seg ^ ((row>>1)&3).
#define STAGE_BYTES 24576
#define SMEM_DYN (4 * STAGE_BYTES)

template<bool G1>
__global__ __launch_bounds__(512, 1) void k_gemm(const float* __restrict__ bias) {
    constexpr int KD = G1 ? DDIM : FDIM;
    constexpr int ND = G1 ? FDIM : DDIM;
    constexpr int NC = KD / 32;

    int e = blockIdx.z;
    int cnt = g_cnt[e];
    int m0 = blockIdx.x * 128;
    if (m0 >= cnt) return;
    int n0 = blockIdx.y * 256;

    const __half* Be = (G1 ? g_w1t : g_w2t) + (size_t)e * ((size_t)KD * ND);

    extern __shared__ char smem[];
    uint32_t sbase = smem_to_u32(smem);

    int tid = threadIdx.x;
    int lane = tid & 31, warp = tid >> 5;
    int wm = warp >> 3, wn = warp & 7;
    int gid = lane >> 2, tig = lane & 3;

    // ---- cp.async source/dst precompute ----
    // A: 128 rows x 4 segs of 16B (8 halves); one per thread.
    int ra = tid >> 2, sa = tid & 3;
    const __half* srcA;
    if (G1) {
        int r = m0 + ra;
        int tk = (r < cnt) ? g_tok[e * 8192 + r] : 0;
        srcA = g_xh + (size_t)tk * KD + sa * 8;
    } else {
        srcA = g_h + (size_t)(e * 8192 + m0 + ra) * KD + sa * 8;
    }
    uint32_t dA = (uint32_t)(ra * 64 + (((sa ^ ((ra >> 1) & 3)) & 3) << 4));
    // B: 256 rows x 4 segs; two per thread.
    const __half* srcB[2];
    uint32_t dB[2];
#pragma unroll
    for (int j = 0; j < 2; j++) {
        int rb = ra + j * 128;
        srcB[j] = Be + (size_t)(n0 + rb) * KD + sa * 8;
        dB[j] = (uint32_t)(8192 + rb * 64 + (((sa ^ ((rb >> 1) & 3)) & 3) << 4));
    }

    // ---- fragment LDS base offsets (segment XOR applied per k-step) ----
    uint32_t baseA[4][2], baseB[4];
#pragma unroll
    for (int mi = 0; mi < 4; mi++)
#pragma unroll
        for (int h = 0; h < 2; h++) {
            int r = wm * 64 + mi * 16 + gid + h * 8;
            baseA[mi][h] = (uint32_t)(r * 64 + (((r >> 1) & 3) << 4) + tig * 4);
        }
#pragma unroll
    for (int ni = 0; ni < 4; ni++) {
        int n = wn * 32 + ni * 8 + gid;
        baseB[ni] = (uint32_t)(8192 + n * 64 + (((n >> 1) & 3) << 4) + tig * 4);
    }

    float acc[4][4][4];
#pragma unroll
    for (int mi = 0; mi < 4; mi++)
#pragma unroll
        for (int ni = 0; ni < 4; ni++)
#pragma unroll
            for (int q = 0; q < 4; q++) acc[mi][ni][q] = 0.f;

    auto issue = [&](int slot, int kt) {
        uint32_t st = sbase + (uint32_t)slot * STAGE_BYTES;
        cp16(st + dA, srcA + kt);
        cp16(st + dB[0], srcB[0] + kt);
        cp16(st + dB[1], srcB[1] + kt);
    };

    issue(0, 0);  CP_COMMIT();
    issue(1, 32); CP_COMMIT();
    issue(2, 64); CP_COMMIT();

#pragma unroll 1
    for (int c = 0; c < NC; c++) {
        CP_WAIT2();
        __syncthreads();
        int pf = c + 3;
        if (pf < NC) issue(pf & 3, pf * 32);
        CP_COMMIT();

        uint32_t st = sbase + (uint32_t)(c & 3) * STAGE_BYTES;
#pragma unroll
        for (int ks = 0; ks < 2; ks++) {
            uint32_t s0 = (uint32_t)(ks * 2) << 4;   // seg for k[0:8)
            uint32_t s1 = s0 ^ 16u;                  // seg for k[8:16)
            uint32_t a[4][4], b[4][2];
#pragma unroll
            for (int mi = 0; mi < 4; mi++) {
                a[mi][0] = lds32(st + (baseA[mi][0] ^ s0));
                a[mi][1] = lds32(st + (baseA[mi][1] ^ s0));
                a[mi][2] = lds32(st + (baseA[mi][0] ^ s1));
                a[mi][3] = lds32(st + (baseA[mi][1] ^ s1));
            }
#pragma unroll
            for (int ni = 0; ni < 4; ni++) {
                b[ni][0] = lds32(st + (baseB[ni] ^ s0));
                b[ni][1] = lds32(st + (baseB[ni] ^ s1));
            }
#pragma unroll
            for (int mi = 0; mi < 4; mi++)
#pragma unroll
                for (int ni = 0; ni < 4; ni++)
                    mma16(acc[mi][ni], a[mi], b[ni]);
        }
    }

    // ---- epilogue ----
    const float* bptr = G1 ? (bias + (size_t)e * ND) : (const float*)nullptr;
#pragma unroll
    for (int mi = 0; mi < 4; mi++) {
        int gr0 = m0 + wm * 64 + mi * 16 + gid;
        int gr1 = gr0 + 8;
        bool v0 = gr0 < cnt, v1 = gr1 < cnt;
#pragma unroll
        for (int ni = 0; ni < 4; ni++) {
            int gc = n0 + wn * 32 + ni * 8 + tig * 2;
            float2 p0 = make_float2(acc[mi][ni][0], acc[mi][ni][1]);
            float2 p1 = make_float2(acc[mi][ni][2], acc[mi][ni][3]);
            if (G1) {
                float bb0 = bptr[gc], bb1 = bptr[gc + 1];
                p0.x += bb0; p0.y += bb1;
                p1.x += bb0; p1.y += bb1;
                p0.x = p0.x / (1.f + __expf(-p0.x));
                p0.y = p0.y / (1.f + __expf(-p0.y));
                p1.x = p1.x / (1.f + __expf(-p1.x));
                p1.y = p1.y / (1.f + __expf(-p1.y));
                __half* h0 = g_h + (size_t)(e * 8192 + gr0) * ND + gc;
                __half* h1 = g_h + (size_t)(e * 8192 + gr1) * ND + gc;
                if (v0) *(__half2*)h0 = __floats2half2_rn(p0.x, p0.y);
                if (v1) *(__half2*)h1 = __floats2half2_rn(p1.x, p1.y);
            } else {
                float* o0 = g_y + (size_t)(e * 8192 + gr0) * ND + gc;
                float* o1 = g_y + (size_t)(e * 8192 + gr1) * ND + gc;
                if (v0) *(float2*)o0 = p0;
                if (v1) *(float2*)o1 = p1;
            }
        }
    }
}

// ---------------- combine ----------------
__global__ void k_combine(float* __restrict__ out, const float* __restrict__ b2) {
    int t = blockIdx.x;
    int s0 = g_slot[t * 2 + 0], s1 = g_slot[t * 2 + 1];
    float w0 = g_w[s0], w1 = g_w[s1];
    int e0 = s0 >> 13, e1 = s1 >> 13;
    const float4* y0 = (const float4*)(g_y + (size_t)s0 * DDIM);
    const float4* y1 = (const float4*)(g_y + (size_t)s1 * DDIM);
    const float4* b20 = (const float4*)(b2 + (size_t)e0 * DDIM);
    const float4* b21 = (const float4*)(b2 + (size_t)e1 * DDIM);
    float4* o = (float4*)(out + (size_t)t * DDIM);
    for (int i = threadIdx.x; i < DDIM / 4; i += 256) {
        float4 a = y0[i], b = y1[i], c0 = b20[i], c1 = b21[i];
        float4 r;
        r.x = w0 * (a.x + c0.x) + w1 * (b.x + c1.x);
        r.y = w0 * (a.y + c0.y) + w1 * (b.y + c1.y);
        r.z = w0 * (a.z + c0.z) + w1 * (b.z + c1.z);
        r.w = w0 * (a.w + c0.w) + w1 * (b.w + c1.w);
        o[i] = r;
    }
}

// ---------------- launch ----------------
extern "C" void kernel_launch(void* const* d_in, const int* in_sizes, int n_in,
                              void* d_out, int out_size) {
    const float* inputs  = (const float*)d_in[0];
    const float* task    = (const float*)d_in[1];
    const float* Wg_in   = (const float*)d_in[2];
    const float* bg_in   = (const float*)d_in[3];
    const float* Wg_task = (const float*)d_in[4];
    const float* bg_task = (const float*)d_in[5];
    const float* alpha   = (const float*)d_in[6];
    const float* W1      = (const float*)d_in[7];
    const float* b1      = (const float*)d_in[8];
    const float* W2      = (const float*)d_in[9];
    const float* b2      = (const float*)d_in[10];
    float* out = (float*)d_out;

    cudaFuncSetAttribute(k_gemm<true>,  cudaFuncAttributeMaxDynamicSharedMemorySize, SMEM_DYN);
    cudaFuncSetAttribute(k_gemm<false>, cudaFuncAttributeMaxDynamicSharedMemorySize, SMEM_DYN);

    k_init<<<1, 32>>>();
    k_taskgate<<<1, 256>>>(task, Wg_task, bg_task);
    k_gate<<<1024, 256>>>(inputs, Wg_in, bg_in, alpha);
    k_laux<<<1, 256>>>(out, out_size);

    // weight transposes (fp32 -> fp16)
    k_tr<true><<<dim3(FDIM / 32, DDIM / 32, NEXP), 256>>>(W1);
    k_tr<false><<<dim3(DDIM / 32, FDIM / 32, NEXP), 256>>>(W2);

    // grouped GEMMs
    k_gemm<true><<<dim3(64, FDIM / 256, NEXP), 512, SMEM_DYN>>>(b1);
    k_gemm<false><<<dim3(64, DDIM / 256, NEXP), 512, SMEM_DYN>>>(nullptr);

    k_combine<<<TOK, 256>>>(out, b2);
}